// round 15
// baseline (speedup 1.0000x reference)
#include <cuda_runtime.h>
#include <cuda_fp16.h>
#include <math.h>

#define NN 4096
#define DD 64
#define BIGF 1e30f
#define NWARP 64           // 64 strips of 64 columns, 1 warp each
#define TSTEPS 4128        // 4096 + 32 (lane skew); 129 chunks of 32
#define FULLM 0xffffffffu

// Diagonal-major cost storage: g_costd[((w*TSTEPS)+ss)*32 + lane] holds the
// half2 cost (c[r][c0], c[r][c0+1]) for r = ss - lane, c0 = w*64 + 2*lane.
__device__ __half2 g_costd[(size_t)NWARP * TSTEPS * 32];   // ~33.8 MB
__device__ float  g_nx[NN];
__device__ float  g_ny[NN];
__device__ float  g_c00;                     // c[0][0] for the virtual corner
__device__ float  g_bnd[NWARP * NN];         // right-column boundary per strip
__device__ int    g_flag[NWARP];             // rows completed per strip

// predicated single store — no BSSY/BSYNC, no compiler memory barrier
__device__ __forceinline__ void st_pred(float* p, float v, int pred) {
    asm volatile("{ .reg .pred p0; setp.ne.s32 p0, %2, 0; @p0 st.global.f32 [%0], %1; }"
                 :: "l"(p), "f"(v), "r"(pred));
}

// ---------------------------------------------------------------------------
__global__ void reset_kernel() {
    if (threadIdx.x < NWARP) g_flag[threadIdx.x] = 0;
}

// ---------------------------------------------------------------------------
__global__ void norms_kernel(const float* __restrict__ x, const float* __restrict__ y) {
    int i = blockIdx.x * blockDim.x + threadIdx.x;
    if (i < NN) {
        const float* p = x + (size_t)i * DD;
        float s = 0.f;
        #pragma unroll
        for (int k = 0; k < DD; k++) s += p[k] * p[k];
        g_nx[i] = s;
    } else if (i < 2 * NN) {
        int j = i - NN;
        const float* p = y + (size_t)j * DD;
        float s = 0.f;
        #pragma unroll
        for (int k = 0; k < DD; k++) s += p[k] * p[k];
        g_ny[j] = s;
    }
}

// ---------------------------------------------------------------------------
// Cost matrix: 64x64 tile per block (tile == strip width), 64 threads,
// 8x8 per thread. Results written directly in diagonal-major layout.
// ---------------------------------------------------------------------------
__global__ void __launch_bounds__(64) cost_kernel(const float* __restrict__ x,
                                                  const float* __restrict__ y) {
    __shared__ float xs[64][65];
    __shared__ float ys[64][65];

    const int I0 = blockIdx.y * 64;
    const int w  = blockIdx.x;          // strip id == column tile id
    const int J0 = w * 64;
    const int tid = threadIdx.x;        // 0..63

    #pragma unroll 4
    for (int it = 0; it < 16; it++) {               // 16*64 float4 = 4096 floats
        int idx = (it * 64 + tid) * 4;
        int r = idx >> 6, k = idx & 63;
        float4 vx = *(const float4*)(x + (size_t)(I0 + r) * DD + k);
        float4 vy = *(const float4*)(y + (size_t)(J0 + r) * DD + k);
        xs[r][k] = vx.x; xs[r][k+1] = vx.y; xs[r][k+2] = vx.z; xs[r][k+3] = vx.w;
        ys[r][k] = vy.x; ys[r][k+1] = vy.y; ys[r][k+2] = vy.z; ys[r][k+3] = vy.w;
    }
    __syncthreads();

    const int tx = tid & 7, ty = tid >> 3;
    const int r0 = ty * 8, c0 = tx * 8;

    float acc[8][8];
    #pragma unroll
    for (int a = 0; a < 8; a++)
        #pragma unroll
        for (int b = 0; b < 8; b++) acc[a][b] = 0.f;

    #pragma unroll 4
    for (int k = 0; k < DD; k++) {
        float ra[8], rb[8];
        #pragma unroll
        for (int a = 0; a < 8; a++) ra[a] = xs[r0 + a][k];
        #pragma unroll
        for (int b = 0; b < 8; b++) rb[b] = ys[c0 + b][k];
        #pragma unroll
        for (int a = 0; a < 8; a++)
            #pragma unroll
            for (int b = 0; b < 8; b++) acc[a][b] = fmaf(ra[a], rb[b], acc[a][b]);
    }

    float nyv[8];
    #pragma unroll
    for (int b = 0; b < 8; b++) nyv[b] = g_ny[J0 + c0 + b];

    #pragma unroll
    for (int a = 0; a < 8; a++) {
        const int i = I0 + r0 + a;
        float nx = g_nx[i];
        #pragma unroll
        for (int b2 = 0; b2 < 4; b2++) {
            float s0 = nx + nyv[2*b2]   - 2.0f * acc[a][2*b2];
            float s1 = nx + nyv[2*b2+1] - 2.0f * acc[a][2*b2+1];
            float e0 = sqrtf(fmaxf(s0, 1e-12f));
            float e1 = sqrtf(fmaxf(s1, 1e-12f));
            const int lane = tx * 4 + b2;          // lane owning these 2 cols
            const int ss = i + lane;               // diagonal step index
            g_costd[((size_t)w * TSTEPS + ss) * 32 + lane] = __floats2half2_rn(e0, e1);
        }
    }

    if (w == 0 && I0 == 0 && tid == 0) {
        float sq = g_nx[0] + g_ny[0] - 2.0f * acc[0][0];   // tid0 owns (0,0)
        g_c00 = sqrtf(fmaxf(sq, 1e-12f));
    }
}

// ---------------------------------------------------------------------------
// Persistent DTW: 64 strips x 1 warp; lane owns 2 adjacent columns; at step
// ss computes row r = ss - lane. Inner loop: ONE shfl + ALU, zero loads.
//  - diag = previous step's left value (register rotate)
//  - lane0 boundary: 1 volatile load/lane/chunk, broadcast via 32 chunk-top
//    shfls into a register array (NEVER multiple volatile loads — they
//    serialize in program order)
//  - costs chunk-staged in a double-buffered register file (R13)
//  - publish every 8 steps to cut flag-rounding lag
// ---------------------------------------------------------------------------
__global__ void __launch_bounds__(32, 1) dtw_kernel(float* __restrict__ out) {
    const int w = blockIdx.x;
    const int lane = threadIdx.x;
    const __half2* cptr = g_costd + (size_t)w * TSTEPS * 32;

    // v1c0/v1c1 = D[prev row][c0/c1]; dg = lfv of previous step (diag)
    float v1c0 = BIGF, v1c1 = BIGF, dg = BIGF;
    if (w == 0 && lane == 0)
        dg = -g_c00;                          // virtual corner seed

    float* bndW = g_bnd + (size_t)w * NN;
    const volatile float* bndp = g_bnd + (size_t)(w > 0 ? w - 1 : 0) * NN;
    const volatile int* vflag = (const volatile int*)&g_flag[w > 0 ? w - 1 : 0];
    int* flagW = &g_flag[w];

    // cost chunk double-buffer: 32 half2 each (current / next chunk)
    __half2 cpC[32], cpN[32];
    #pragma unroll
    for (int k = 0; k < 32; k++) cpC[k] = cptr[(size_t)k * 32 + lane];
    #pragma unroll
    for (int k = 0; k < 32; k++) cpN[k] = cptr[(size_t)(32 + k) * 32 + lane];

    const bool l0 = (lane == 0);
    const bool l31 = (lane == 31);

    for (int cs = 0; cs < TSTEPS; cs += 32) {
        // chunk poll + ONE volatile boundary load per lane, then broadcast
        float bval = BIGF;
        if (w > 0 && cs < NN) {
            while (*vflag < cs + 32) { }
            bval = bndp[cs + lane];           // single volatile load
        }
        float bq[32];
        #pragma unroll
        for (int j = 0; j < 32; j++) bq[j] = __shfl_sync(FULLM, bval, j);

        const int rb = cs - lane;

        #pragma unroll
        for (int g = 0; g < 4; g++) {
            #pragma unroll
            for (int q = 0; q < 8; q++) {
                const int k = g * 8 + q;
                const int r = rb + k;

                float lfs = __shfl_up_sync(FULLM, v1c1, 1);
                float lfv = l0 ? bq[k] : lfs;

                float2 cc = __half22float2(cpC[k]);

                float n0 = fminf(fminf(fmaf(2.f, cc.x, dg),   v1c0 + cc.x), lfv + cc.x);
                float n1 = fminf(fminf(fmaf(2.f, cc.y, v1c0), v1c1 + cc.y), n0 + cc.y);

                const bool act = ((unsigned)r < NN);
                v1c0 = act ? n0 : v1c0;
                v1c1 = act ? n1 : v1c1;
                dg = lfv;                      // diag for step ss+1

                int rcl = r < 0 ? 0 : (r > NN - 1 ? NN - 1 : r);
                st_pred(bndW + rcl, n1, (int)(act && l31));
            }
            // publish after each 8-step group: lane31 completed rows
            // 0 .. (cs + g*8+7 - 31)  =>  flag = cs + g*8 - 23
            {
                int fv = cs + g * 8 - 23;
                if (l31 && fv > 0) {
                    __threadfence();
                    atomicExch(flagW, fv);
                }
            }
        }

        // rotate buffers; refill cpN with chunk cs+64 (a full chunk of slack)
        #pragma unroll
        for (int k = 0; k < 32; k++) cpC[k] = cpN[k];
        if (cs + 64 < TSTEPS) {
            const size_t base = (size_t)(cs + 64) * 32 + lane;
            #pragma unroll
            for (int k = 0; k < 32; k++)
                cpN[k] = cptr[base + (size_t)k * 32];
        }
    }

    // final publish so strip w+1 can finish its last rows
    if (l31) {
        __threadfence();
        atomicExch(flagW, NN);
    }

    if (w == NWARP - 1 && l31)
        out[0] = v1c1;          // D[4095][4095]
}

// ---------------------------------------------------------------------------
extern "C" void kernel_launch(void* const* d_in, const int* in_sizes, int n_in,
                              void* d_out, int out_size) {
    const float* x = (const float*)d_in[0];
    const float* y = (const float*)d_in[1];
    float* out = (float*)d_out;

    reset_kernel<<<1, 64>>>();
    norms_kernel<<<(2 * NN + 511) / 512, 512>>>(x, y);
    cost_kernel<<<dim3(NN / 64, NN / 64), 64>>>(x, y);
    dtw_kernel<<<NWARP, 32>>>(out);
}

// round 16
// speedup vs baseline: 1.1578x; 1.1578x over previous
#include <cuda_runtime.h>
#include <cuda_fp16.h>
#include <math.h>

#define NN 4096
#define DD 64
#define BIGF 1e30f
#define NWARP 64           // 64 strips of 64 columns, 1 warp each
#define TSUP 1056          // super-steps: (4096/4-1)+31 = 1054 last active; 132 chunks of 8
#define FULLM 0xffffffffu

// Batched diagonal cost storage: g_costd4[((w*TSUP)+S)*32 + lane] is a uint4
// holding half2 costs for rows r0..r0+3 (r0 = 4*(S-lane)) of the lane's two
// columns c0 = w*64 + 2*lane, c1 = c0+1:
//   .x = half2(c[r0][c0],   c[r0][c1])    .y = half2(c[r0+1][c0], c[r0+1][c1])
//   .z = half2(c[r0+2][c0], c[r0+2][c1])  .w = half2(c[r0+3][c0], c[r0+3][c1])
__device__ uint4  g_costd4[(size_t)NWARP * TSUP * 32];     // ~34.6 MB
__device__ float  g_nx[NN];
__device__ float  g_ny[NN];
__device__ float  g_c00;                     // c[0][0] for the virtual corner
__device__ __align__(256) float g_bnd[NWARP * NN];   // right-col boundary per strip
__device__ int    g_flag[NWARP];             // rows published per strip

// predicated 16B vector store — no BSSY/BSYNC
__device__ __forceinline__ void st_pred4(float* p, float a, float b, float c,
                                         float d, int pred) {
    asm volatile("{ .reg .pred p0; setp.ne.s32 p0, %5, 0; "
                 "@p0 st.global.v4.f32 [%0], {%1,%2,%3,%4}; }"
                 :: "l"(p), "f"(a), "f"(b), "f"(c), "f"(d), "r"(pred));
}

// ---------------------------------------------------------------------------
__global__ void reset_kernel() {
    if (threadIdx.x < NWARP) g_flag[threadIdx.x] = 0;
}

// ---------------------------------------------------------------------------
__global__ void norms_kernel(const float* __restrict__ x, const float* __restrict__ y) {
    int i = blockIdx.x * blockDim.x + threadIdx.x;
    if (i < NN) {
        const float* p = x + (size_t)i * DD;
        float s = 0.f;
        #pragma unroll
        for (int k = 0; k < DD; k++) s += p[k] * p[k];
        g_nx[i] = s;
    } else if (i < 2 * NN) {
        int j = i - NN;
        const float* p = y + (size_t)j * DD;
        float s = 0.f;
        #pragma unroll
        for (int k = 0; k < DD; k++) s += p[k] * p[k];
        g_ny[j] = s;
    }
}

// ---------------------------------------------------------------------------
// Cost matrix: 64x64 tile per block (tile == strip width), 64 threads,
// 8x8 per thread. Written directly in the batched diagonal layout.
// ---------------------------------------------------------------------------
__global__ void __launch_bounds__(64) cost_kernel(const float* __restrict__ x,
                                                  const float* __restrict__ y) {
    __shared__ float xs[64][65];
    __shared__ float ys[64][65];

    const int I0 = blockIdx.y * 64;
    const int w  = blockIdx.x;          // strip id == column tile id
    const int J0 = w * 64;
    const int tid = threadIdx.x;        // 0..63

    #pragma unroll 4
    for (int it = 0; it < 16; it++) {               // 16*64 float4 = 4096 floats
        int idx = (it * 64 + tid) * 4;
        int r = idx >> 6, k = idx & 63;
        float4 vx = *(const float4*)(x + (size_t)(I0 + r) * DD + k);
        float4 vy = *(const float4*)(y + (size_t)(J0 + r) * DD + k);
        xs[r][k] = vx.x; xs[r][k+1] = vx.y; xs[r][k+2] = vx.z; xs[r][k+3] = vx.w;
        ys[r][k] = vy.x; ys[r][k+1] = vy.y; ys[r][k+2] = vy.z; ys[r][k+3] = vy.w;
    }
    __syncthreads();

    const int tx = tid & 7, ty = tid >> 3;
    const int r0 = ty * 8, c0 = tx * 8;

    float acc[8][8];
    #pragma unroll
    for (int a = 0; a < 8; a++)
        #pragma unroll
        for (int b = 0; b < 8; b++) acc[a][b] = 0.f;

    #pragma unroll 4
    for (int k = 0; k < DD; k++) {
        float ra[8], rb[8];
        #pragma unroll
        for (int a = 0; a < 8; a++) ra[a] = xs[r0 + a][k];
        #pragma unroll
        for (int b = 0; b < 8; b++) rb[b] = ys[c0 + b][k];
        #pragma unroll
        for (int a = 0; a < 8; a++)
            #pragma unroll
            for (int b = 0; b < 8; b++) acc[a][b] = fmaf(ra[a], rb[b], acc[a][b]);
    }

    float nyv[8];
    #pragma unroll
    for (int b = 0; b < 8; b++) nyv[b] = g_ny[J0 + c0 + b];

    unsigned* gc = (unsigned*)g_costd4;
    #pragma unroll
    for (int a = 0; a < 8; a++) {
        const int i = I0 + r0 + a;
        float nx = g_nx[i];
        #pragma unroll
        for (int b2 = 0; b2 < 4; b2++) {
            float s0 = nx + nyv[2*b2]   - 2.0f * acc[a][2*b2];
            float s1 = nx + nyv[2*b2+1] - 2.0f * acc[a][2*b2+1];
            float e0 = sqrtf(fmaxf(s0, 1e-12f));
            float e1 = sqrtf(fmaxf(s1, 1e-12f));
            __half2 h = __floats2half2_rn(e0, e1);
            const int ln = tx * 4 + b2;            // lane owning these 2 cols
            const int S  = (i >> 2) + ln;          // super-step index
            gc[(((size_t)w * TSUP + S) * 32 + ln) * 4 + (i & 3)] = *(unsigned*)&h;
        }
    }

    if (w == 0 && I0 == 0 && tid == 0) {
        float sq = g_nx[0] + g_ny[0] - 2.0f * acc[0][0];   // tid0 owns (0,0)
        g_c00 = sqrtf(fmaxf(sq, 1e-12f));
    }
}

// ---------------------------------------------------------------------------
// Persistent DTW, diamond-batched: 64 strips x 1 warp; lane owns 2 cols and
// computes 4 rows per super-step (rows 4(S-lane)..+3). The 4 left values are
// the neighbor's 4 right-edge outputs from the previous super-step: 4
// INDEPENDENT shfl_ups (latency paid once, not per row). Diag values come
// from the received batch (L[k-1]; carried L3). Costs chunk-staged in
// double-buffered uint4 registers. Fence cadence: 1 per 8-super-step chunk.
// ---------------------------------------------------------------------------
__global__ void __launch_bounds__(32, 1) dtw_kernel(float* __restrict__ out) {
    const int w = blockIdx.x;
    const int lane = threadIdx.x;
    const uint4* cptr = g_costd4 + (size_t)w * TSUP * 32;

    // t0,t1 = D[last row][c0/c1]; R0..R3 = right-edge outputs of my batch
    float t0 = BIGF, t1 = BIGF, dgTop = BIGF;
    float R0 = BIGF, R1 = BIGF, R2 = BIGF, R3 = BIGF;
    if (w == 0 && lane == 0)
        dgTop = -g_c00;                       // virtual corner seed

    float* bndW = g_bnd + (size_t)w * NN;
    const volatile float* bndp = g_bnd + (size_t)(w > 0 ? w - 1 : 0) * NN;
    const volatile int* vflag = (const volatile int*)&g_flag[w > 0 ? w - 1 : 0];
    int* flagW = &g_flag[w];

    // cost chunk double-buffer: 8 uint4 each (current / next chunk)
    uint4 cpC[8], cpN[8];
    #pragma unroll
    for (int k = 0; k < 8; k++) cpC[k] = cptr[(size_t)k * 32 + lane];
    #pragma unroll
    for (int k = 0; k < 8; k++) cpN[k] = cptr[(size_t)(8 + k) * 32 + lane];

    const bool l0 = (lane == 0);
    const bool l31 = (lane == 31);

    for (int cs = 0; cs < TSUP; cs += 8) {
        // chunk poll + ONE volatile boundary load per lane (rows 4cs..4cs+31)
        float bval = BIGF;
        if (w > 0 && 4 * cs < NN) {
            int need = 4 * cs + 32; if (need > NN) need = NN;
            while (*vflag < need) { }
            int bi = 4 * cs + lane; if (bi > NN - 1) bi = NN - 1;
            bval = bndp[bi];
        }

        #pragma unroll
        for (int q = 0; q < 8; q++) {
            const int S = cs + q;
            const int r0 = 4 * (S - lane);

            // batched neighbor exchange: 4 independent shfls
            float L0 = __shfl_up_sync(FULLM, R0, 1);
            float L1 = __shfl_up_sync(FULLM, R1, 1);
            float L2 = __shfl_up_sync(FULLM, R2, 1);
            float L3 = __shfl_up_sync(FULLM, R3, 1);
            // lane0 boundary extraction (independent broadcasts)
            float b0 = __shfl_sync(FULLM, bval, 4 * q);
            float b1 = __shfl_sync(FULLM, bval, 4 * q + 1);
            float b2 = __shfl_sync(FULLM, bval, 4 * q + 2);
            float b3 = __shfl_sync(FULLM, bval, 4 * q + 3);
            L0 = l0 ? b0 : L0;
            L1 = l0 ? b1 : L1;
            L2 = l0 ? b2 : L2;
            L3 = l0 ? b3 : L3;

            const uint4 cq = cpC[q];
            float2 cA = __half22float2(*(const __half2*)&cq.x);
            float2 cB = __half22float2(*(const __half2*)&cq.y);
            float2 cC = __half22float2(*(const __half2*)&cq.z);
            float2 cD = __half22float2(*(const __half2*)&cq.w);

            // row r0   (diag=dgTop, up=(t0,t1), left=L0)
            float n0 = fminf(fminf(fmaf(2.f, cA.x, dgTop), t0 + cA.x), L0 + cA.x);
            float n1 = fminf(fminf(fmaf(2.f, cA.y, t0),    t1 + cA.y), n0 + cA.y);
            // row r0+1 (diag=L0, up=(n0,n1), left=L1)
            float m0 = fminf(fminf(fmaf(2.f, cB.x, L0),  n0 + cB.x), L1 + cB.x);
            float m1 = fminf(fminf(fmaf(2.f, cB.y, n0),  n1 + cB.y), m0 + cB.y);
            // row r0+2 (diag=L1, up=(m0,m1), left=L2)
            float p0 = fminf(fminf(fmaf(2.f, cC.x, L1),  m0 + cC.x), L2 + cC.x);
            float p1 = fminf(fminf(fmaf(2.f, cC.y, m0),  m1 + cC.y), p0 + cC.y);
            // row r0+3 (diag=L2, up=(p0,p1), left=L3)
            float g0 = fminf(fminf(fmaf(2.f, cD.x, L2),  p0 + cD.x), L3 + cD.x);
            float g1 = fminf(fminf(fmaf(2.f, cD.y, p0),  p1 + cD.y), g0 + cD.y);

            const bool act = ((unsigned)r0 < NN);    // r0 mult of 4 => whole batch
            R0 = act ? n1 : R0;
            R1 = act ? m1 : R1;
            R2 = act ? p1 : R2;
            R3 = act ? g1 : R3;
            t0 = act ? g0 : t0;
            t1 = act ? g1 : t1;
            dgTop = act ? L3 : dgTop;

            int rcl = r0 < 0 ? 0 : (r0 > NN - 4 ? NN - 4 : r0);
            st_pred4(bndW + rcl, n1, m1, p1, g1, (int)(act && l31));
        }

        // rotate buffers; refill cpN with chunk cs+16 (full chunk of slack)
        #pragma unroll
        for (int k = 0; k < 8; k++) cpC[k] = cpN[k];
        if (cs + 16 < TSUP) {
            const size_t base = (size_t)(cs + 16) * 32 + lane;
            #pragma unroll
            for (int k = 0; k < 8; k++)
                cpN[k] = cptr[base + (size_t)k * 32];
        }

        // publish once per chunk: lane31 completed rows 0..4(cs+7-31)+3
        if (l31) {
            int fv = 4 * (cs + 7) - 120;
            if (fv > 0) {
                __threadfence();
                atomicExch(flagW, fv);
            }
        }
    }

    if (w == NWARP - 1 && l31)
        out[0] = t1;            // D[4095][4095]
}

// ---------------------------------------------------------------------------
extern "C" void kernel_launch(void* const* d_in, const int* in_sizes, int n_in,
                              void* d_out, int out_size) {
    const float* x = (const float*)d_in[0];
    const float* y = (const float*)d_in[1];
    float* out = (float*)d_out;

    reset_kernel<<<1, 64>>>();
    norms_kernel<<<(2 * NN + 511) / 512, 512>>>(x, y);
    cost_kernel<<<dim3(NN / 64, NN / 64), 64>>>(x, y);
    dtw_kernel<<<NWARP, 32>>>(out);
}